// round 1
// baseline (speedup 1.0000x reference)
#include <cuda_runtime.h>
#include <cuda_bf16.h>

// Problem shape (fixed by setup_inputs): x is [B, T] float32.
#define BB 64
#define TT 262144
#define LL 512            // chunk length (samples per thread)
#define CC 512            // chunks per row; LL*CC == TT
#define NCHUNK (BB*CC)    // 32768 threads in pass1/pass3

// Scratch: chunk-end states from pass1 (zero-IC), corrected chunk-start states
// from pass2. Layout: [b*CC + k][2] = (y[L-1], y[L-2]) resp. (y[-1], y[-2]).
__device__ float g_endstate[NCHUNK * 2];
__device__ float g_startstate[NCHUNK * 2];

// ---------------------------------------------------------------------------
// Pass 1: per-chunk recurrence with zero initial y-state. FIR taps use the
// true global x (zero only at global n<0), so only the IIR state needs fixup.
// ---------------------------------------------------------------------------
__global__ __launch_bounds__(128) void k_pass1(
    const float* __restrict__ x,
    const float* __restrict__ ac,
    const float* __restrict__ bc,
    float* __restrict__ endstate)
{
    int t = blockIdx.x * 128 + threadIdx.x;
    if (t >= NCHUNK) return;
    int b = t / CC;
    int k = t - b * CC;

    float inv = 1.0f / ac[0];
    float na1 = -ac[1] * inv, na2 = -ac[2] * inv;
    float b0 = bc[0] * inv, b1 = bc[1] * inv, b2 = bc[2] * inv;

    const float* xb = x + (size_t)b * TT + (size_t)k * LL;
    float xm1 = 0.f, xm2 = 0.f;
    if (k) { xm1 = xb[-1]; xm2 = xb[-2]; }

    float y1 = 0.f, y2 = 0.f;
    const float4* xv = reinterpret_cast<const float4*>(xb);
#pragma unroll 4
    for (int i = 0; i < LL / 4; ++i) {
        float4 v = xv[i];
        float f0 = fmaf(b1, xm1, fmaf(b2, xm2, b0 * v.x));
        float ya = fmaf(na1, y1, fmaf(na2, y2, f0));
        float f1 = fmaf(b1, v.x, fmaf(b2, xm1, b0 * v.y));
        float yb = fmaf(na1, ya, fmaf(na2, y1, f1));
        float f2 = fmaf(b1, v.y, fmaf(b2, v.x, b0 * v.z));
        float yc = fmaf(na1, yb, fmaf(na2, ya, f2));
        float f3 = fmaf(b1, v.z, fmaf(b2, v.y, b0 * v.w));
        float yd = fmaf(na1, yc, fmaf(na2, yb, f3));
        y2 = yc; y1 = yd;
        xm2 = v.z; xm1 = v.w;
    }
    endstate[t * 2 + 0] = y1;   // y[L-1] under zero IC
    endstate[t * 2 + 1] = y2;   // y[L-2] under zero IC
}

// ---------------------------------------------------------------------------
// Pass 2: one block. Thread 0 builds Phi = M^LL (M = [[-a1,-a2],[1,0]]) by
// repeated squaring in double; then 64 threads (one per batch row) run the
// sequential chunk-combine:  s_{k+1} = Phi * s_k + end_k,  s_0 = 0,
// writing each chunk's corrected START state.
// ---------------------------------------------------------------------------
__global__ __launch_bounds__(64) void k_pass2(
    const float* __restrict__ ac,
    const float* __restrict__ endstate,
    float* __restrict__ startstate)
{
    __shared__ float phi[4];
    if (threadIdx.x == 0) {
        double a0 = (double)ac[0];
        double a1 = (double)ac[1] / a0, a2 = (double)ac[2] / a0;
        double m11 = -a1, m12 = -a2, m21 = 1.0, m22 = 0.0;
        // LL = 512 = 2^9 -> 9 squarings
        for (int i = 0; i < 9; ++i) {
            double n11 = m11 * m11 + m12 * m21;
            double n12 = m11 * m12 + m12 * m22;
            double n21 = m21 * m11 + m22 * m21;
            double n22 = m21 * m12 + m22 * m22;
            m11 = n11; m12 = n12; m21 = n21; m22 = n22;
        }
        phi[0] = (float)m11; phi[1] = (float)m12;
        phi[2] = (float)m21; phi[3] = (float)m22;
    }
    __syncthreads();

    int b = threadIdx.x;
    if (b >= BB) return;
    float p11 = phi[0], p12 = phi[1], p21 = phi[2], p22 = phi[3];
    float s1 = 0.f, s2 = 0.f;   // (y[-1], y[-2]) entering chunk k
    for (int k = 0; k < CC; ++k) {
        int idx = (b * CC + k) * 2;
        startstate[idx + 0] = s1;
        startstate[idx + 1] = s2;
        float d1 = endstate[idx + 0];
        float d2 = endstate[idx + 1];
        float e1 = fmaf(p11, s1, fmaf(p12, s2, d1));
        float e2 = fmaf(p21, s1, fmaf(p22, s2, d2));
        s1 = e1; s2 = e2;
    }
}

// ---------------------------------------------------------------------------
// Pass 3: rerun each chunk with corrected initial state; clip, scale, store.
// ---------------------------------------------------------------------------
__global__ __launch_bounds__(128) void k_pass3(
    const float* __restrict__ x,
    const float* __restrict__ ac,
    const float* __restrict__ bc,
    const float* __restrict__ gainp,
    const float* __restrict__ startstate,
    float* __restrict__ out)
{
    int t = blockIdx.x * 128 + threadIdx.x;
    if (t >= NCHUNK) return;
    int b = t / CC;
    int k = t - b * CC;

    float inv = 1.0f / ac[0];
    float na1 = -ac[1] * inv, na2 = -ac[2] * inv;
    float b0 = bc[0] * inv, b1 = bc[1] * inv, b2 = bc[2] * inv;
    float gain = gainp[0];

    const float* xb = x + (size_t)b * TT + (size_t)k * LL;
    float* ob = out + (size_t)b * TT + (size_t)k * LL;
    float xm1 = 0.f, xm2 = 0.f;
    if (k) { xm1 = xb[-1]; xm2 = xb[-2]; }

    float y1 = startstate[t * 2 + 0];
    float y2 = startstate[t * 2 + 1];

    const float4* xv = reinterpret_cast<const float4*>(xb);
    float4* ov = reinterpret_cast<float4*>(ob);
#pragma unroll 4
    for (int i = 0; i < LL / 4; ++i) {
        float4 v = xv[i];
        float f0 = fmaf(b1, xm1, fmaf(b2, xm2, b0 * v.x));
        float ya = fmaf(na1, y1, fmaf(na2, y2, f0));
        float f1 = fmaf(b1, v.x, fmaf(b2, xm1, b0 * v.y));
        float yb = fmaf(na1, ya, fmaf(na2, y1, f1));
        float f2 = fmaf(b1, v.y, fmaf(b2, v.x, b0 * v.z));
        float yc = fmaf(na1, yb, fmaf(na2, ya, f2));
        float f3 = fmaf(b1, v.z, fmaf(b2, v.y, b0 * v.w));
        float yd = fmaf(na1, yc, fmaf(na2, yb, f3));
        float4 o;
        o.x = gain * fminf(1.f, fmaxf(-1.f, ya));
        o.y = gain * fminf(1.f, fmaxf(-1.f, yb));
        o.z = gain * fminf(1.f, fmaxf(-1.f, yc));
        o.w = gain * fminf(1.f, fmaxf(-1.f, yd));
        ov[i] = o;
        y2 = yc; y1 = yd;
        xm2 = v.z; xm1 = v.w;
    }
}

extern "C" void kernel_launch(void* const* d_in, const int* in_sizes, int n_in,
                              void* d_out, int out_size)
{
    const float* x    = (const float*)d_in[0];
    const float* ac   = (const float*)d_in[1];
    const float* bc   = (const float*)d_in[2];
    const float* gain = (const float*)d_in[3];
    float* out = (float*)d_out;

    float* endstate;
    float* startstate;
    cudaGetSymbolAddress((void**)&endstate, g_endstate);
    cudaGetSymbolAddress((void**)&startstate, g_startstate);

    int grid = (NCHUNK + 127) / 128;
    k_pass1<<<grid, 128>>>(x, ac, bc, endstate);
    k_pass2<<<1, 64>>>(ac, endstate, startstate);
    k_pass3<<<grid, 128>>>(x, ac, bc, gain, startstate, out);
}

// round 4
// speedup vs baseline: 1.9537x; 1.9537x over previous
#include <cuda_runtime.h>

// x is [B, T] float32.
#define BB 64
#define TT 262144
#define THREADS 256
#define SEG 32
#define BLK_SAMP (THREADS * SEG)   // 8192 samples per block
#define CPB (TT / BLK_SAMP)        // 32 block-chunks per row
#define NBLK (BB * CPB)            // 2048 blocks

// Per-block zero-IC end states / corrected start states, kept in DOUBLE.
__device__ double g_end[NBLK * 2];
__device__ double g_start[NBLK * 2];

struct Coef { float na1, na2, b0, b1, b2; };

__device__ __forceinline__ Coef load_coef(const float* ac, const float* bc) {
    Coef c; float inv = 1.0f / ac[0];
    c.na1 = -ac[1] * inv; c.na2 = -ac[2] * inv;
    c.b0 = bc[0] * inv; c.b1 = bc[1] * inv; c.b2 = bc[2] * inv;
    return c;
}

// Padded smem index: sample j lives at (j/32)*33 + j%32 (conflict-free).
__device__ __forceinline__ int padidx(int j) { return (j >> 5) * 33 + (j & 31); }

// Thread 0 helper: fill sLev[r][0..3] = Phi^(32*2^r) for r=0..7 (double).
__device__ __forceinline__ void build_levels(const float* ac, double* sLev) {
    double a0 = (double)ac[0];
    double a1 = (double)ac[1] / a0, a2 = (double)ac[2] / a0;
    double m11 = -a1, m12 = -a2, m21 = 1.0, m22 = 0.0;   // Phi
    for (int i = 0; i < 5; ++i) {                         // -> Phi^32
        double n11 = m11*m11 + m12*m21, n12 = m11*m12 + m12*m22;
        double n21 = m21*m11 + m22*m21, n22 = m21*m12 + m22*m22;
        m11 = n11; m12 = n12; m21 = n21; m22 = n22;
    }
    sLev[0] = m11; sLev[1] = m12; sLev[2] = m21; sLev[3] = m22;
    for (int r = 1; r < 8; ++r) {                         // square up
        double n11 = m11*m11 + m12*m21, n12 = m11*m12 + m12*m22;
        double n21 = m21*m11 + m22*m21, n22 = m21*m12 + m22*m22;
        m11 = n11; m12 = n12; m21 = n21; m22 = n22;
        sLev[r*4+0] = m11; sLev[r*4+1] = m12; sLev[r*4+2] = m21; sLev[r*4+3] = m22;
    }
}

// ---------------------------------------------------------------------------
// Pass 1: block zero-IC end state. fp32 local recurrence + DOUBLE vector scan.
// ---------------------------------------------------------------------------
__global__ __launch_bounds__(THREADS) void k_pass1(
    const float* __restrict__ x,
    const float* __restrict__ ac,
    const float* __restrict__ bc)
{
    __shared__ float   sx[THREADS * 33];   // 33 KB
    __shared__ double2 sV[THREADS];        // 4 KB
    __shared__ double  sLev[8 * 4];

    int bid = blockIdx.x;
    int row = bid / CPB, blk = bid - row * CPB;
    size_t base = (size_t)row * TT + (size_t)blk * BLK_SAMP;
    int tid = threadIdx.x;

    const float4* xv = reinterpret_cast<const float4*>(x + base);
    for (int i = tid * 4; i < BLK_SAMP; i += THREADS * 4) {
        float4 v = xv[i >> 2];
        int p = padidx(i);
        sx[p] = v.x; sx[p + 1] = v.y; sx[p + 2] = v.z; sx[p + 3] = v.w;
    }
    if (tid == 0) build_levels(ac, sLev);
    __syncthreads();

    Coef c = load_coef(ac, bc);

    float xm1, xm2;
    if (tid == 0) {
        if (blk) { xm1 = x[base - 1]; xm2 = x[base - 2]; }
        else     { xm1 = 0.f; xm2 = 0.f; }
    } else {
        xm1 = sx[(tid - 1) * 33 + 31];
        xm2 = sx[(tid - 1) * 33 + 30];
    }

    int boff = tid * 33;
    float y1 = 0.f, y2 = 0.f, a = xm1, b = xm2;
#pragma unroll
    for (int j = 0; j < SEG; ++j) {
        float xc = sx[boff + j];
        float f = fmaf(c.b1, a, fmaf(c.b2, b, c.b0 * xc));
        float y = fmaf(c.na1, y1, fmaf(c.na2, y2, f));
        y2 = y1; y1 = y; b = a; a = xc;
    }

    // Vector-only Kogge-Stone in double: v <- Phi^(32*2^r) * v_src + v.
    double v1 = (double)y1, v2 = (double)y2;
#pragma unroll
    for (int r = 0; r < 8; ++r) {
        sV[tid] = make_double2(v1, v2);
        __syncthreads();
        int src = tid - (1 << r);
        double2 vp;
        bool has = (src >= 0);
        if (has) vp = sV[src];
        __syncthreads();
        if (has) {
            double m11 = sLev[r*4+0], m12 = sLev[r*4+1];
            double m21 = sLev[r*4+2], m22 = sLev[r*4+3];
            v1 = m11 * vp.x + m12 * vp.y + v1;
            v2 = m21 * vp.x + m22 * vp.y + v2;
        }
    }
    if (tid == THREADS - 1) {
        g_end[bid * 2 + 0] = v1;
        g_end[bid * 2 + 1] = v2;
    }
}

// ---------------------------------------------------------------------------
// Pass 2: inter-block combine (32 steps/row, double), states staged in smem.
// ---------------------------------------------------------------------------
__global__ __launch_bounds__(256) void k_pass2(const float* __restrict__ ac)
{
    __shared__ double sEnd[NBLK * 2];  // 32 KB
    __shared__ double dphi[4];
    int tid = threadIdx.x;

    for (int i = tid; i < NBLK * 2; i += 256) sEnd[i] = g_end[i];
    if (tid == 0) {
        // Phi^8192 (13 squarings) in double.
        double a0 = (double)ac[0];
        double a1 = (double)ac[1] / a0, a2 = (double)ac[2] / a0;
        double m11 = -a1, m12 = -a2, m21 = 1.0, m22 = 0.0;
        for (int i = 0; i < 13; ++i) {
            double n11 = m11*m11 + m12*m21, n12 = m11*m12 + m12*m22;
            double n21 = m21*m11 + m22*m21, n22 = m21*m12 + m22*m22;
            m11 = n11; m12 = n12; m21 = n21; m22 = n22;
        }
        dphi[0] = m11; dphi[1] = m12; dphi[2] = m21; dphi[3] = m22;
    }
    __syncthreads();

    if (tid < BB) {
        double p11 = dphi[0], p12 = dphi[1], p21 = dphi[2], p22 = dphi[3];
        double s1 = 0.0, s2 = 0.0;
        int base = tid * CPB;
        for (int k = 0; k < CPB; ++k) {
            int idx = (base + k) * 2;
            g_start[idx + 0] = s1;
            g_start[idx + 1] = s2;
            double d1 = sEnd[idx], d2 = sEnd[idx + 1];
            double n1 = p11 * s1 + p12 * s2 + d1;
            double n2 = p21 * s1 + p22 * s2 + d2;
            s1 = n1; s2 = n2;
        }
    }
}

// ---------------------------------------------------------------------------
// Pass 3: double scan -> per-thread entry state -> fp32 recompute, clip, gain.
// ---------------------------------------------------------------------------
__global__ __launch_bounds__(THREADS) void k_pass3(
    const float* __restrict__ x,
    const float* __restrict__ ac,
    const float* __restrict__ bc,
    const float* __restrict__ gainp,
    float* __restrict__ out)
{
    __shared__ float   sx[THREADS * 33];
    __shared__ double2 sV[THREADS];
    __shared__ double  sLev[8 * 4];

    int bid = blockIdx.x;
    int row = bid / CPB, blk = bid - row * CPB;
    size_t base = (size_t)row * TT + (size_t)blk * BLK_SAMP;
    int tid = threadIdx.x;

    const float4* xv = reinterpret_cast<const float4*>(x + base);
    for (int i = tid * 4; i < BLK_SAMP; i += THREADS * 4) {
        float4 v = xv[i >> 2];
        int p = padidx(i);
        sx[p] = v.x; sx[p + 1] = v.y; sx[p + 2] = v.z; sx[p + 3] = v.w;
    }
    if (tid == 0) build_levels(ac, sLev);
    __syncthreads();

    Coef c = load_coef(ac, bc);
    float gain = gainp[0];

    float xm1, xm2;
    if (tid == 0) {
        if (blk) { xm1 = x[base - 1]; xm2 = x[base - 2]; }
        else     { xm1 = 0.f; xm2 = 0.f; }
    } else {
        xm1 = sx[(tid - 1) * 33 + 31];
        xm2 = sx[(tid - 1) * 33 + 30];
    }
    float sxm1 = xm1, sxm2 = xm2;   // keep for the recompute

    int boff = tid * 33;
    float y1 = 0.f, y2 = 0.f, a = xm1, b = xm2;
#pragma unroll
    for (int j = 0; j < SEG; ++j) {
        float xc = sx[boff + j];
        float f = fmaf(c.b1, a, fmaf(c.b2, b, c.b0 * xc));
        float y = fmaf(c.na1, y1, fmaf(c.na2, y2, f));
        y2 = y1; y1 = y; b = a; a = xc;
    }

    double v1 = (double)y1, v2 = (double)y2;
#pragma unroll
    for (int r = 0; r < 8; ++r) {
        sV[tid] = make_double2(v1, v2);
        __syncthreads();
        int src = tid - (1 << r);
        double2 vp;
        bool has = (src >= 0);
        if (has) vp = sV[src];
        __syncthreads();
        if (has) {
            double m11 = sLev[r*4+0], m12 = sLev[r*4+1];
            double m21 = sLev[r*4+2], m22 = sLev[r*4+3];
            v1 = m11 * vp.x + m12 * vp.y + v1;
            v2 = m21 * vp.x + m22 * vp.y + v2;
        }
    }
    // Exclusive vector prefix: inclusive value of tid-1.
    sV[tid] = make_double2(v1, v2);
    __syncthreads();
    double e1 = 0.0, e2 = 0.0;
    if (tid > 0) { double2 t = sV[tid - 1]; e1 = t.x; e2 = t.y; }

    // w = Phi^(32*tid) * S via binary decomposition over precomputed levels.
    double w1 = g_start[bid * 2 + 0];
    double w2 = g_start[bid * 2 + 1];
#pragma unroll
    for (int r = 0; r < 8; ++r) {
        if ((tid >> r) & 1) {
            double m11 = sLev[r*4+0], m12 = sLev[r*4+1];
            double m21 = sLev[r*4+2], m22 = sLev[r*4+3];
            double n1 = m11 * w1 + m12 * w2;
            double n2 = m21 * w1 + m22 * w2;
            w1 = n1; w2 = n2;
        }
    }
    float s1 = (float)(w1 + e1);
    float s2 = (float)(w2 + e2);
    __syncthreads();   // all reads of sV / neighbor sx done before overwrite

    // Corrected recompute; write clipped*gain output in-place into sx.
    y1 = s1; y2 = s2; a = sxm1; b = sxm2;
#pragma unroll
    for (int j = 0; j < SEG; ++j) {
        float xc = sx[boff + j];
        float f = fmaf(c.b1, a, fmaf(c.b2, b, c.b0 * xc));
        float y = fmaf(c.na1, y1, fmaf(c.na2, y2, f));
        sx[boff + j] = gain * fminf(1.f, fmaxf(-1.f, y));
        y2 = y1; y1 = y; b = a; a = xc;
    }
    __syncthreads();

    float4* ov = reinterpret_cast<float4*>(out + base);
    for (int i = tid * 4; i < BLK_SAMP; i += THREADS * 4) {
        int p = padidx(i);
        float4 o;
        o.x = sx[p]; o.y = sx[p + 1]; o.z = sx[p + 2]; o.w = sx[p + 3];
        ov[i >> 2] = o;
    }
}

extern "C" void kernel_launch(void* const* d_in, const int* in_sizes, int n_in,
                              void* d_out, int out_size)
{
    const float* x    = (const float*)d_in[0];
    const float* ac   = (const float*)d_in[1];
    const float* bc   = (const float*)d_in[2];
    const float* gain = (const float*)d_in[3];
    float* out = (float*)d_out;

    k_pass1<<<NBLK, THREADS>>>(x, ac, bc);
    k_pass2<<<1, 256>>>(ac);
    k_pass3<<<NBLK, THREADS>>>(x, ac, bc, gain, out);
}

// round 5
// speedup vs baseline: 2.4550x; 1.2566x over previous
#include <cuda_runtime.h>

// x is [B, T] float32.
#define BB 64
#define TT 262144
#define WSPAN 4096                 // samples per warp
#define TILES (WSPAN / 128)        // 32 serial tiles of 128 samples per warp
#define CPR (TT / WSPAN)           // 64 chunks per row
#define NW (BB * CPR)              // 4096 warps
#define WPB 4                      // warps per block
#define NBLK (NW / WPB)            // 1024 blocks

// Chunk end states (zero-IC) and corrected chunk start states, y-space double:
// s = (y[last], y[last-1]).
__device__ double2 g_end[NW];
__device__ double2 g_start[NW];

struct SC {
    float2 lvl[5];        // c^(4*2^r), r=0..4   (c = alpha + i*beta, pole)
    float  alpha, beta, invbeta;
    float  na1, na2, b0, b1, b2;
    double d_alpha, d_beta, d_invbeta;
    double d_c128r, d_c128i;      // c^128 in double (cross-tile carry)
};

__device__ __forceinline__ void build_sc(const float* ac, const float* bc, SC* sc) {
    double a0 = (double)ac[0];
    double a1 = (double)ac[1] / a0, a2 = (double)ac[2] / a0;
    double al = -0.5 * a1;
    double be = sqrt(a2 - al * al);      // r*sin(theta) > 0 for resonator
    sc->d_alpha = al; sc->d_beta = be; sc->d_invbeta = 1.0 / be;
    sc->alpha = (float)al; sc->beta = (float)be; sc->invbeta = (float)(1.0 / be);
    sc->na1 = (float)(-a1); sc->na2 = (float)(-a2);
    sc->b0 = (float)((double)bc[0] / a0);
    sc->b1 = (float)((double)bc[1] / a0);
    sc->b2 = (float)((double)bc[2] / a0);
    // c^4 then squarings
    double cr = al, ci = be;
    for (int i = 0; i < 2; ++i) { double nr = cr*cr - ci*ci, ni = 2.0*cr*ci; cr = nr; ci = ni; }
    for (int r = 0; r < 5; ++r) {
        sc->lvl[r] = make_float2((float)cr, (float)ci);
        double nr = cr*cr - ci*ci, ni = 2.0*cr*ci; cr = nr; ci = ni;
    }
    sc->d_c128r = cr; sc->d_c128i = ci;   // c^128
}

__device__ __forceinline__ float2 cmulf(float2 a, float2 b) {
    return make_float2(fmaf(a.x, b.x, -a.y * b.y), fmaf(a.x, b.y, a.y * b.x));
}

// ---------------------------------------------------------------------------
// Pass 1: per-warp zero-IC end state. Shuffle-only; lane0 keeps double carry.
// ---------------------------------------------------------------------------
__global__ __launch_bounds__(128) void k_pass1(
    const float* __restrict__ x,
    const float* __restrict__ ac,
    const float* __restrict__ bc)
{
    __shared__ SC sc;
    if (threadIdx.x == 0) build_sc(ac, bc, &sc);
    __syncthreads();

    int wid = blockIdx.x * WPB + (threadIdx.x >> 5);
    int lane = threadIdx.x & 31;
    int row = wid / CPR, chunk = wid - row * CPR;
    size_t wbase = (size_t)row * TT + (size_t)chunk * WSPAN;
    const float4* xv = reinterpret_cast<const float4*>(x + wbase);

    float na1 = sc.na1, na2 = sc.na2, b0 = sc.b0, b1 = sc.b1, b2 = sc.b2;
    float alpha = sc.alpha, invbeta = sc.invbeta;
    float2 L0 = sc.lvl[0], L1 = sc.lvl[1], L2 = sc.lvl[2], L3 = sc.lvl[3], L4 = sc.lvl[4];

    // previous-sample carry registers (last two x of previous tile)
    float pv_w = 0.f, pv_z = 0.f;
    if (chunk) { pv_w = x[wbase - 1]; pv_z = x[wbase - 2]; }

    double cu1 = 0.0, cu2 = 0.0;          // lane0: warp zero-IC state in u (double)
    double c128r = sc.d_c128r, c128i = sc.d_c128i;

    float4 v0 = xv[lane];
    float4 v1 = xv[32 + lane];
#pragma unroll 4
    for (int t = 0; t < TILES; ++t) {
        float4 v = v0;
        v0 = v1;
        if (t + 2 < TILES) v1 = xv[(t + 2) * 32 + lane];

        float xm1 = __shfl_up_sync(0xffffffffu, v.w, 1);
        float xm2 = __shfl_up_sync(0xffffffffu, v.z, 1);
        if (lane == 0) { xm1 = pv_w; xm2 = pv_z; }

        // local 4-step zero-IC recurrence (y-space fp32)
        float f0 = fmaf(b1, xm1, fmaf(b2, xm2, b0 * v.x));
        float ya = f0;
        float f1 = fmaf(b1, v.x, fmaf(b2, xm1, b0 * v.y));
        float yb = fmaf(na1, ya, f1);
        float f2 = fmaf(b1, v.y, fmaf(b2, v.x, b0 * v.z));
        float yc = fmaf(na1, yb, fmaf(na2, ya, f2));
        float f3 = fmaf(b1, v.z, fmaf(b2, v.y, b0 * v.w));
        float yd = fmaf(na1, yc, fmaf(na2, yb, f3));

        // u = P^{-1}(yd, yc):  u1 = yc, u2 = (alpha*yc - yd)*invbeta
        float2 uv = make_float2(yc, fmaf(alpha, yc, -yd) * invbeta);

        // 5-round shuffle reduce: new[l] = c^(4*2^r)*val[l] + val[l+2^r]
#pragma unroll
        for (int r = 0; r < 5; ++r) {
            float2 L = (r == 0) ? L0 : (r == 1) ? L1 : (r == 2) ? L2 : (r == 3) ? L3 : L4;
            float rx = __shfl_down_sync(0xffffffffu, uv.x, 1 << r);
            float ry = __shfl_down_sync(0xffffffffu, uv.y, 1 << r);
            float nx = fmaf(L.x, uv.x, fmaf(-L.y, uv.y, rx));
            float ny = fmaf(L.y, uv.x, fmaf(L.x, uv.y, ry));
            uv = make_float2(nx, ny);
        }
        // lane0 now holds the full tile value; update double carry on lane0
        if (lane == 0) {
            double n1 = c128r * cu1 - c128i * cu2 + (double)uv.x;
            double n2 = c128i * cu1 + c128r * cu2 + (double)uv.y;
            cu1 = n1; cu2 = n2;
        }
        pv_w = __shfl_sync(0xffffffffu, v.w, 31);
        pv_z = __shfl_sync(0xffffffffu, v.z, 31);
    }
    if (lane == 0) {
        // y-space: y[last] = alpha*u1 - beta*u2, y[last-1] = u1
        double y1 = sc.d_alpha * cu1 - sc.d_beta * cu2;
        g_end[wid] = make_double2(y1, cu1);
    }
}

// ---------------------------------------------------------------------------
// Pass 2: per-row serial combine of 64 chunk states (double), smem staged.
// ---------------------------------------------------------------------------
__global__ __launch_bounds__(64) void k_pass2(const float* __restrict__ ac)
{
    __shared__ double2 sEnd[CPR];
    int row = blockIdx.x, tid = threadIdx.x;
    if (tid < CPR) sEnd[tid] = g_end[row * CPR + tid];
    __syncthreads();
    if (tid == 0) {
        double a0 = (double)ac[0];
        double a1 = (double)ac[1] / a0, a2 = (double)ac[2] / a0;
        double m11 = -a1, m12 = -a2, m21 = 1.0, m22 = 0.0;
        for (int i = 0; i < 12; ++i) {     // Phi^4096 = Phi^(2^12)
            double n11 = m11*m11 + m12*m21, n12 = m11*m12 + m12*m22;
            double n21 = m21*m11 + m22*m21, n22 = m21*m12 + m22*m22;
            m11 = n11; m12 = n12; m21 = n21; m22 = n22;
        }
        double s1 = 0.0, s2 = 0.0;
        for (int k = 0; k < CPR; ++k) {
            g_start[row * CPR + k] = make_double2(s1, s2);
            double2 d = sEnd[k];
            double n1 = m11 * s1 + m12 * s2 + d.x;
            double n2 = m21 * s1 + m22 * s2 + d.y;
            s1 = n1; s2 = n2;
        }
    }
}

// ---------------------------------------------------------------------------
// Pass 3: per-warp corrected recompute; shuffle scan for per-lane entry states.
// ---------------------------------------------------------------------------
__global__ __launch_bounds__(128) void k_pass3(
    const float* __restrict__ x,
    const float* __restrict__ ac,
    const float* __restrict__ bc,
    const float* __restrict__ gainp,
    float* __restrict__ out)
{
    __shared__ SC sc;
    if (threadIdx.x == 0) build_sc(ac, bc, &sc);
    __syncthreads();

    int wid = blockIdx.x * WPB + (threadIdx.x >> 5);
    int lane = threadIdx.x & 31;
    int row = wid / CPR, chunk = wid - row * CPR;
    size_t wbase = (size_t)row * TT + (size_t)chunk * WSPAN;
    const float4* xv = reinterpret_cast<const float4*>(x + wbase);
    float4* ov = reinterpret_cast<float4*>(out + wbase);

    float na1 = sc.na1, na2 = sc.na2, b0 = sc.b0, b1 = sc.b1, b2 = sc.b2;
    float alpha = sc.alpha, beta = sc.beta, invbeta = sc.invbeta;
    float gain = gainp[0];
    float2 L0 = sc.lvl[0], L1 = sc.lvl[1], L2 = sc.lvl[2], L3 = sc.lvl[3], L4 = sc.lvl[4];

    // per-lane offset c^(4*lane)
    float2 off = make_float2(1.f, 0.f);
    if (lane & 1)  off = cmulf(off, L0);
    if (lane & 2)  off = cmulf(off, L1);
    if (lane & 4)  off = cmulf(off, L2);
    if (lane & 8)  off = cmulf(off, L3);
    if (lane & 16) off = cmulf(off, L4);

    float pv_w = 0.f, pv_z = 0.f;
    if (chunk) { pv_w = x[wbase - 1]; pv_z = x[wbase - 2]; }

    // warp entry state (y-space double) -> u-space double carry on lane0
    double2 S = g_start[wid];
    double cu1 = S.y;
    double cu2 = (sc.d_alpha * S.y - S.x) * sc.d_invbeta;
    double c128r = sc.d_c128r, c128i = sc.d_c128i;

    float4 v0 = xv[lane];
    float4 v1 = xv[32 + lane];
#pragma unroll 4
    for (int t = 0; t < TILES; ++t) {
        float4 v = v0;
        v0 = v1;
        if (t + 2 < TILES) v1 = xv[(t + 2) * 32 + lane];

        float xm1 = __shfl_up_sync(0xffffffffu, v.w, 1);
        float xm2 = __shfl_up_sync(0xffffffffu, v.z, 1);
        if (lane == 0) { xm1 = pv_w; xm2 = pv_z; }

        // local zero-IC (for scan)
        float f0 = fmaf(b1, xm1, fmaf(b2, xm2, b0 * v.x));
        float f1 = fmaf(b1, v.x, fmaf(b2, xm1, b0 * v.y));
        float f2 = fmaf(b1, v.y, fmaf(b2, v.x, b0 * v.z));
        float f3 = fmaf(b1, v.z, fmaf(b2, v.y, b0 * v.w));
        float ya = f0;
        float yb = fmaf(na1, ya, f1);
        float yc = fmaf(na1, yb, fmaf(na2, ya, f2));
        float yd = fmaf(na1, yc, fmaf(na2, yb, f3));

        float2 uv = make_float2(yc, fmaf(alpha, yc, -yd) * invbeta);

        // Kogge-Stone inclusive scan (shfl_up)
#pragma unroll
        for (int r = 0; r < 5; ++r) {
            float2 L = (r == 0) ? L0 : (r == 1) ? L1 : (r == 2) ? L2 : (r == 3) ? L3 : L4;
            float px = __shfl_up_sync(0xffffffffu, uv.x, 1 << r);
            float py = __shfl_up_sync(0xffffffffu, uv.y, 1 << r);
            if (lane >= (1 << r)) {
                uv.x = fmaf(L.x, px, fmaf(-L.y, py, uv.x));
                uv.y = fmaf(L.y, px, fmaf(L.x, py, uv.y));
            }
        }
        // exclusive prefix
        float Ex = __shfl_up_sync(0xffffffffu, uv.x, 1);
        float Ey = __shfl_up_sync(0xffffffffu, uv.y, 1);
        if (lane == 0) { Ex = 0.f; Ey = 0.f; }

        // broadcast tile-entry carry (fp32) from lane0
        float cfx = __shfl_sync(0xffffffffu, (float)cu1, 0);
        float cfy = __shfl_sync(0xffffffffu, (float)cu2, 0);

        // per-lane entry state in u: off*carry + E
        float e1 = fmaf(off.x, cfx, fmaf(-off.y, cfy, Ex));
        float e2 = fmaf(off.y, cfx, fmaf(off.x, cfy, Ey));
        // back to y: y[n-1] = alpha*e1 - beta*e2, y[n-2] = e1
        float yp1 = fmaf(alpha, e1, -beta * e2);
        float yp2 = e1;

        // corrected recompute of 4 samples
        float z0 = fmaf(na1, yp1, fmaf(na2, yp2, f0));
        float z1 = fmaf(na1, z0, fmaf(na2, yp1, f1));
        float z2 = fmaf(na1, z1, fmaf(na2, z0, f2));
        float z3 = fmaf(na1, z2, fmaf(na2, z1, f3));

        float4 o;
        o.x = gain * fminf(1.f, fmaxf(-1.f, z0));
        o.y = gain * fminf(1.f, fmaxf(-1.f, z1));
        o.z = gain * fminf(1.f, fmaxf(-1.f, z2));
        o.w = gain * fminf(1.f, fmaxf(-1.f, z3));
        ov[t * 32 + lane] = o;

        // update double carry on lane0 with tile-inclusive (lane 31's value)
        float I31x = __shfl_sync(0xffffffffu, uv.x, 31);
        float I31y = __shfl_sync(0xffffffffu, uv.y, 31);
        if (lane == 0) {
            double n1 = c128r * cu1 - c128i * cu2 + (double)I31x;
            double n2 = c128i * cu1 + c128r * cu2 + (double)I31y;
            cu1 = n1; cu2 = n2;
        }
        pv_w = __shfl_sync(0xffffffffu, v.w, 31);
        pv_z = __shfl_sync(0xffffffffu, v.z, 31);
    }
}

extern "C" void kernel_launch(void* const* d_in, const int* in_sizes, int n_in,
                              void* d_out, int out_size)
{
    const float* x    = (const float*)d_in[0];
    const float* ac   = (const float*)d_in[1];
    const float* bc   = (const float*)d_in[2];
    const float* gain = (const float*)d_in[3];
    float* out = (float*)d_out;

    k_pass1<<<NBLK, 128>>>(x, ac, bc);
    k_pass2<<<BB, 64>>>(ac);
    k_pass3<<<NBLK, 128>>>(x, ac, bc, gain, out);
}

// round 7
// speedup vs baseline: 2.5027x; 1.0194x over previous
#include <cuda_runtime.h>

// x is [B, T] float32.
#define BB 64
#define TT 262144
#define WSPAN 2048                 // samples per warp
#define TILES (WSPAN / 128)        // 16 serial tiles of 128 samples
#define CPR (TT / WSPAN)           // 128 chunks per row
#define NW (BB * CPR)              // 8192 warps
#define WPB 4                      // warps per block
#define NBLK (NW / WPB)            // 2048 blocks

// Chunk end states (zero-IC) / corrected start states, y-space double:
// (y[last], y[last-1]).
__device__ double2 g_end[NW];
__device__ double2 g_start[NW];

struct SC {
    float2 lvl[5];     // c^(4*2^r)
    float2 ilvl[5];    // c^(-4*2^r)
    float2 i4;         // c^-4
    float  alpha, beta, invbeta;
    float  na1, na2, b0, b1, b2;
    double d_alpha, d_beta, d_invbeta;
    double c128r, c128i;   // c^128
};

__device__ __forceinline__ void build_sc(const float* ac, const float* bc, SC* sc) {
    double a0 = (double)ac[0];
    double a1 = (double)ac[1] / a0, a2 = (double)ac[2] / a0;
    double al = -0.5 * a1;
    double be = sqrt(a2 - al * al);          // r*sin(theta) > 0
    sc->d_alpha = al; sc->d_beta = be; sc->d_invbeta = 1.0 / be;
    sc->alpha = (float)al; sc->beta = (float)be; sc->invbeta = (float)(1.0 / be);
    sc->na1 = (float)(-a1); sc->na2 = (float)(-a2);
    sc->b0 = (float)((double)bc[0] / a0);
    sc->b1 = (float)((double)bc[1] / a0);
    sc->b2 = (float)((double)bc[2] / a0);

    double cr = al, ci = be;                 // c
    for (int i = 0; i < 2; ++i) { double nr = cr*cr - ci*ci, ni = 2.0*cr*ci; cr = nr; ci = ni; }
    for (int r = 0; r < 5; ++r) {
        sc->lvl[r] = make_float2((float)cr, (float)ci);
        double n = cr*cr + ci*ci;            // inverse = conj / |.|^2
        sc->ilvl[r] = make_float2((float)(cr / n), (float)(-ci / n));
        if (r == 0) sc->i4 = sc->ilvl[0];
        double nr = cr*cr - ci*ci, ni = 2.0*cr*ci; cr = nr; ci = ni;
    }
    sc->c128r = cr; sc->c128i = ci;          // c^128
}

__device__ __forceinline__ float2 cmulf(float2 a, float2 b) {
    return make_float2(fmaf(a.x, b.x, -a.y * b.y), fmaf(a.x, b.y, a.y * b.x));
}

// ---------------------------------------------------------------------------
// Pass 1: per-warp zero-IC end state. Scaled-basis reduce (complex SUM only).
// Convention: w_j = b_j * c^(-4(j+1));  tile total S = sum_j w_j;
//             carry update C' = c^128 * (C + S).
// ---------------------------------------------------------------------------
__global__ __launch_bounds__(128, 10) void k_pass1(
    const float* __restrict__ x,
    const float* __restrict__ ac,
    const float* __restrict__ bc)
{
    __shared__ SC sc;
    if (threadIdx.x == 0) build_sc(ac, bc, &sc);
    __syncthreads();

    int wid = blockIdx.x * WPB + (threadIdx.x >> 5);
    int lane = threadIdx.x & 31;
    int row = wid / CPR, chunk = wid - row * CPR;
    size_t wbase = (size_t)row * TT + (size_t)chunk * WSPAN;
    const float4* xv = reinterpret_cast<const float4*>(x + wbase);

    float na1 = sc.na1, na2 = sc.na2, b0 = sc.b0, b1 = sc.b1, b2 = sc.b2;
    float alpha = sc.alpha, invbeta = sc.invbeta;

    // sd = c^(-4*(lane+1))
    float2 sd = sc.i4;
    if (lane & 1)  sd = cmulf(sd, sc.ilvl[0]);
    if (lane & 2)  sd = cmulf(sd, sc.ilvl[1]);
    if (lane & 4)  sd = cmulf(sd, sc.ilvl[2]);
    if (lane & 8)  sd = cmulf(sd, sc.ilvl[3]);
    if (lane & 16) sd = cmulf(sd, sc.ilvl[4]);

    float pv_w = 0.f, pv_z = 0.f;
    if (chunk) { pv_w = x[wbase - 1]; pv_z = x[wbase - 2]; }

    double cu1 = 0.0, cu2 = 0.0;      // lane0: u-space carry (double)
    double c128r = sc.c128r, c128i = sc.c128i;

    float4 v0 = xv[lane];
    float4 v1 = xv[32 + lane];
#pragma unroll 4
    for (int t = 0; t < TILES; ++t) {
        float4 v = v0;
        v0 = v1;
        if (t + 2 < TILES) v1 = xv[(t + 2) * 32 + lane];

        float xm1 = __shfl_up_sync(0xffffffffu, v.w, 1);
        float xm2 = __shfl_up_sync(0xffffffffu, v.z, 1);
        if (lane == 0) { xm1 = pv_w; xm2 = pv_z; }

        float f0 = fmaf(b1, xm1, fmaf(b2, xm2, b0 * v.x));
        float f1 = fmaf(b1, v.x, fmaf(b2, xm1, b0 * v.y));
        float f2 = fmaf(b1, v.y, fmaf(b2, v.x, b0 * v.z));
        float f3 = fmaf(b1, v.z, fmaf(b2, v.y, b0 * v.w));
        float ya = f0;
        float yb = fmaf(na1, ya, f1);
        float yc = fmaf(na1, yb, fmaf(na2, ya, f2));
        float yd = fmaf(na1, yc, fmaf(na2, yb, f3));

        // b_j in u-space: u = (yc, (alpha*yc - yd)*invbeta); w = u * sd
        float2 u = make_float2(yc, fmaf(alpha, yc, -yd) * invbeta);
        float2 w = cmulf(u, sd);

        // complex sum reduce -> lane0 holds S
#pragma unroll
        for (int s = 16; s > 0; s >>= 1) {
            w.x += __shfl_down_sync(0xffffffffu, w.x, s);
            w.y += __shfl_down_sync(0xffffffffu, w.y, s);
        }
        if (lane == 0) {
            double t1 = cu1 + (double)w.x;
            double t2 = cu2 + (double)w.y;
            cu1 = c128r * t1 - c128i * t2;
            cu2 = c128i * t1 + c128r * t2;
        }
        pv_w = __shfl_sync(0xffffffffu, v.w, 31);
        pv_z = __shfl_sync(0xffffffffu, v.z, 31);
    }
    if (lane == 0) {
        double y1 = sc.d_alpha * cu1 - sc.d_beta * cu2;
        g_end[wid] = make_double2(y1, cu1);
    }
}

// ---------------------------------------------------------------------------
// Pass 2: per-row serial combine of 128 chunk states (double), smem staged.
// ---------------------------------------------------------------------------
__global__ __launch_bounds__(128) void k_pass2(const float* __restrict__ ac)
{
    __shared__ double2 sEnd[CPR];
    int row = blockIdx.x, tid = threadIdx.x;
    if (tid < CPR) sEnd[tid] = g_end[row * CPR + tid];
    __syncthreads();
    if (tid == 0) {
        double a0 = (double)ac[0];
        double a1 = (double)ac[1] / a0, a2 = (double)ac[2] / a0;
        double m11 = -a1, m12 = -a2, m21 = 1.0, m22 = 0.0;
        for (int i = 0; i < 11; ++i) {     // Phi^2048
            double n11 = m11*m11 + m12*m21, n12 = m11*m12 + m12*m22;
            double n21 = m21*m11 + m22*m21, n22 = m21*m12 + m22*m22;
            m11 = n11; m12 = n12; m21 = n21; m22 = n22;
        }
        double s1 = 0.0, s2 = 0.0;
        for (int k = 0; k < CPR; ++k) {
            g_start[row * CPR + k] = make_double2(s1, s2);
            double2 d = sEnd[k];
            double n1 = m11 * s1 + m12 * s2 + d.x;
            double n2 = m21 * s1 + m22 * s2 + d.y;
            s1 = n1; s2 = n2;
        }
    }
}

// ---------------------------------------------------------------------------
// Pass 3: per-warp corrected recompute; scaled-basis prefix-sum scan.
// entry_u(lane l) = (C + exclusive_l) * c^(4l); carry C' = c^128*(C + S).
// ---------------------------------------------------------------------------
__global__ __launch_bounds__(128, 10) void k_pass3(
    const float* __restrict__ x,
    const float* __restrict__ ac,
    const float* __restrict__ bc,
    const float* __restrict__ gainp,
    float* __restrict__ out)
{
    __shared__ SC sc;
    if (threadIdx.x == 0) build_sc(ac, bc, &sc);
    __syncthreads();

    int wid = blockIdx.x * WPB + (threadIdx.x >> 5);
    int lane = threadIdx.x & 31;
    int row = wid / CPR, chunk = wid - row * CPR;
    size_t wbase = (size_t)row * TT + (size_t)chunk * WSPAN;
    const float4* xv = reinterpret_cast<const float4*>(x + wbase);
    float4* ov = reinterpret_cast<float4*>(out + wbase);

    float na1 = sc.na1, na2 = sc.na2, b0 = sc.b0, b1 = sc.b1, b2 = sc.b2;
    float alpha = sc.alpha, beta = sc.beta, invbeta = sc.invbeta;
    float gain = gainp[0];

    // sd = c^(-4*(lane+1)); su = c^(4*lane)
    float2 sd = sc.i4, su = make_float2(1.f, 0.f);
    if (lane & 1)  { sd = cmulf(sd, sc.ilvl[0]); su = cmulf(su, sc.lvl[0]); }
    if (lane & 2)  { sd = cmulf(sd, sc.ilvl[1]); su = cmulf(su, sc.lvl[1]); }
    if (lane & 4)  { sd = cmulf(sd, sc.ilvl[2]); su = cmulf(su, sc.lvl[2]); }
    if (lane & 8)  { sd = cmulf(sd, sc.ilvl[3]); su = cmulf(su, sc.lvl[3]); }
    if (lane & 16) { sd = cmulf(sd, sc.ilvl[4]); su = cmulf(su, sc.lvl[4]); }

    float pv_w = 0.f, pv_z = 0.f;
    if (chunk) { pv_w = x[wbase - 1]; pv_z = x[wbase - 2]; }

    // warp entry state -> u-space double carry on lane0
    double2 S0 = g_start[wid];
    double cu1 = S0.y;
    double cu2 = (sc.d_alpha * S0.y - S0.x) * sc.d_invbeta;
    double c128r = sc.c128r, c128i = sc.c128i;

    float4 v0 = xv[lane];
    float4 v1 = xv[32 + lane];
#pragma unroll 4
    for (int t = 0; t < TILES; ++t) {
        float4 v = v0;
        v0 = v1;
        if (t + 2 < TILES) v1 = xv[(t + 2) * 32 + lane];

        float xm1 = __shfl_up_sync(0xffffffffu, v.w, 1);
        float xm2 = __shfl_up_sync(0xffffffffu, v.z, 1);
        if (lane == 0) { xm1 = pv_w; xm2 = pv_z; }

        float f0 = fmaf(b1, xm1, fmaf(b2, xm2, b0 * v.x));
        float f1 = fmaf(b1, v.x, fmaf(b2, xm1, b0 * v.y));
        float f2 = fmaf(b1, v.y, fmaf(b2, v.x, b0 * v.z));
        float f3 = fmaf(b1, v.z, fmaf(b2, v.y, b0 * v.w));
        float ya = f0;
        float yb = fmaf(na1, ya, f1);
        float yc = fmaf(na1, yb, fmaf(na2, ya, f2));
        float yd = fmaf(na1, yc, fmaf(na2, yb, f3));

        float2 u = make_float2(yc, fmaf(alpha, yc, -yd) * invbeta);
        float2 w = cmulf(u, sd);

        // inclusive prefix SUM (complex adds only)
#pragma unroll
        for (int s = 1; s < 32; s <<= 1) {
            float px = __shfl_up_sync(0xffffffffu, w.x, s);
            float py = __shfl_up_sync(0xffffffffu, w.y, s);
            if (lane >= s) { w.x += px; w.y += py; }
        }
        float Sx = __shfl_sync(0xffffffffu, w.x, 31);   // tile total S
        float Sy = __shfl_sync(0xffffffffu, w.y, 31);
        // exclusive prefix
        float ex = __shfl_up_sync(0xffffffffu, w.x, 1);
        float ey = __shfl_up_sync(0xffffffffu, w.y, 1);
        if (lane == 0) { ex = 0.f; ey = 0.f; }

        // broadcast carry C (fp32) from lane0
        float cfx = __shfl_sync(0xffffffffu, (float)cu1, 0);
        float cfy = __shfl_sync(0xffffffffu, (float)cu2, 0);

        // entry_u = (C + exclusive) * c^(4*lane)
        float2 e = cmulf(make_float2(cfx + ex, cfy + ey), su);
        float yp1 = fmaf(alpha, e.x, -beta * e.y);   // y[n-1]
        float yp2 = e.x;                             // y[n-2]

        float z0 = fmaf(na1, yp1, fmaf(na2, yp2, f0));
        float z1 = fmaf(na1, z0, fmaf(na2, yp1, f1));
        float z2 = fmaf(na1, z1, fmaf(na2, z0, f2));
        float z3 = fmaf(na1, z2, fmaf(na2, z1, f3));

        float4 o;
        o.x = gain * fminf(1.f, fmaxf(-1.f, z0));
        o.y = gain * fminf(1.f, fmaxf(-1.f, z1));
        o.z = gain * fminf(1.f, fmaxf(-1.f, z2));
        o.w = gain * fminf(1.f, fmaxf(-1.f, z3));
        ov[t * 32 + lane] = o;

        if (lane == 0) {
            double t1 = cu1 + (double)Sx;
            double t2 = cu2 + (double)Sy;
            cu1 = c128r * t1 - c128i * t2;
            cu2 = c128i * t1 + c128r * t2;
        }
        pv_w = __shfl_sync(0xffffffffu, v.w, 31);
        pv_z = __shfl_sync(0xffffffffu, v.z, 31);
    }
}

extern "C" void kernel_launch(void* const* d_in, const int* in_sizes, int n_in,
                              void* d_out, int out_size)
{
    const float* x    = (const float*)d_in[0];
    const float* ac   = (const float*)d_in[1];
    const float* bc   = (const float*)d_in[2];
    const float* gain = (const float*)d_in[3];
    float* out = (float*)d_out;

    k_pass1<<<NBLK, 128>>>(x, ac, bc);
    k_pass2<<<BB, 128>>>(ac);
    k_pass3<<<NBLK, 128>>>(x, ac, bc, gain, out);
}

// round 8
// speedup vs baseline: 2.7885x; 1.1142x over previous
#include <cuda_runtime.h>

// x is [B, T] float32.
#define BB 64
#define TT 262144
#define WSPAN 1024                 // samples per warp
#define TILES 4                    // 4 serial tiles of 256 samples (8/lane)
#define CPR (TT / WSPAN)           // 256 chunks per row
#define NW (BB * CPR)              // 16384 warps
#define WPB 4                      // warps per block
#define NBLK (NW / WPB)            // 4096 blocks

// Chunk end states (zero-IC) / corrected start states, y-space double:
// (y[last], y[last-1]).
__device__ double2 g_end[NW];
__device__ double2 g_start[NW];

struct SC {
    float2 lvl[5];     // c^(8*2^r), r=0..4
    float2 ilvl[5];    // c^(-8*2^r)
    float2 i8;         // c^-8
    float  alpha, beta, invbeta;
    float  na1, na2, b0, b1, b2;
    double d_alpha, d_beta, d_invbeta;
    double c256r, c256i;   // c^256 (tile advance)
};

__device__ __forceinline__ void build_sc(const float* ac, const float* bc, SC* sc) {
    double a0 = (double)ac[0];
    double a1 = (double)ac[1] / a0, a2 = (double)ac[2] / a0;
    double al = -0.5 * a1;
    double be = sqrt(a2 - al * al);          // r*sin(theta) > 0
    sc->d_alpha = al; sc->d_beta = be; sc->d_invbeta = 1.0 / be;
    sc->alpha = (float)al; sc->beta = (float)be; sc->invbeta = (float)(1.0 / be);
    sc->na1 = (float)(-a1); sc->na2 = (float)(-a2);
    sc->b0 = (float)((double)bc[0] / a0);
    sc->b1 = (float)((double)bc[1] / a0);
    sc->b2 = (float)((double)bc[2] / a0);

    double cr = al, ci = be;                 // c
    for (int i = 0; i < 3; ++i) { double nr = cr*cr - ci*ci, ni = 2.0*cr*ci; cr = nr; ci = ni; } // c^8
    for (int r = 0; r < 5; ++r) {
        sc->lvl[r] = make_float2((float)cr, (float)ci);
        double n = cr*cr + ci*ci;            // inverse = conj/|.|^2
        sc->ilvl[r] = make_float2((float)(cr / n), (float)(-ci / n));
        if (r == 0) sc->i8 = sc->ilvl[0];
        double nr = cr*cr - ci*ci, ni = 2.0*cr*ci; cr = nr; ci = ni;
    }
    sc->c256r = cr; sc->c256i = ci;          // c^256
}

__device__ __forceinline__ float2 cmulf(float2 a, float2 b) {
    return make_float2(fmaf(a.x, b.x, -a.y * b.y), fmaf(a.x, b.y, a.y * b.x));
}

// 8-sample FIR terms from x0..x7 (va,vb) and two previous samples.
#define FIR8(f, va, vb, xm1, xm2, b0, b1, b2)                         \
    f[0] = fmaf(b1, xm1,  fmaf(b2, xm2,  b0 * va.x));                 \
    f[1] = fmaf(b1, va.x, fmaf(b2, xm1,  b0 * va.y));                 \
    f[2] = fmaf(b1, va.y, fmaf(b2, va.x, b0 * va.z));                 \
    f[3] = fmaf(b1, va.z, fmaf(b2, va.y, b0 * va.w));                 \
    f[4] = fmaf(b1, va.w, fmaf(b2, va.z, b0 * vb.x));                 \
    f[5] = fmaf(b1, vb.x, fmaf(b2, va.w, b0 * vb.y));                 \
    f[6] = fmaf(b1, vb.y, fmaf(b2, vb.x, b0 * vb.z));                 \
    f[7] = fmaf(b1, vb.z, fmaf(b2, vb.y, b0 * vb.w));

// ---------------------------------------------------------------------------
// Pass 1: per-warp zero-IC end state. Scaled-basis complex-sum reduce.
// w_j = b_j * c^(-8(j+1)); S = sum_j w_j; carry C' = c^256 * (C + S).
// ---------------------------------------------------------------------------
__global__ __launch_bounds__(128, 8) void k_pass1(
    const float* __restrict__ x,
    const float* __restrict__ ac,
    const float* __restrict__ bc)
{
    __shared__ SC sc;
    if (threadIdx.x == 0) build_sc(ac, bc, &sc);
    __syncthreads();

    int wid = blockIdx.x * WPB + (threadIdx.x >> 5);
    int lane = threadIdx.x & 31;
    int row = wid / CPR, chunk = wid - row * CPR;
    size_t wbase = (size_t)row * TT + (size_t)chunk * WSPAN;
    const float4* xv = reinterpret_cast<const float4*>(x + wbase);

    float na1 = sc.na1, na2 = sc.na2, b0 = sc.b0, b1 = sc.b1, b2 = sc.b2;
    float alpha = sc.alpha, invbeta = sc.invbeta;

    // sd = c^(-8*(lane+1))
    float2 sd = sc.i8;
    if (lane & 1)  sd = cmulf(sd, sc.ilvl[0]);
    if (lane & 2)  sd = cmulf(sd, sc.ilvl[1]);
    if (lane & 4)  sd = cmulf(sd, sc.ilvl[2]);
    if (lane & 8)  sd = cmulf(sd, sc.ilvl[3]);
    if (lane & 16) sd = cmulf(sd, sc.ilvl[4]);

    float pv_w = 0.f, pv_z = 0.f;
    if (chunk) { pv_w = x[wbase - 1]; pv_z = x[wbase - 2]; }

    double cu1 = 0.0, cu2 = 0.0;      // lane0 u-space carry (double)
    double c256r = sc.c256r, c256i = sc.c256i;

    float4 va = xv[2 * lane], vb = xv[2 * lane + 1];
#pragma unroll
    for (int t = 0; t < TILES; ++t) {
        float4 nva, nvb;
        if (t + 1 < TILES) {
            nva = xv[(t + 1) * 64 + 2 * lane];
            nvb = xv[(t + 1) * 64 + 2 * lane + 1];
        }
        float xm1 = __shfl_up_sync(0xffffffffu, vb.w, 1);
        float xm2 = __shfl_up_sync(0xffffffffu, vb.z, 1);
        if (lane == 0) { xm1 = pv_w; xm2 = pv_z; }

        float f[8];
        FIR8(f, va, vb, xm1, xm2, b0, b1, b2);

        float y0 = f[0];
        float y1 = fmaf(na1, y0, f[1]);
        float y2 = fmaf(na1, y1, fmaf(na2, y0, f[2]));
        float y3 = fmaf(na1, y2, fmaf(na2, y1, f[3]));
        float y4 = fmaf(na1, y3, fmaf(na2, y2, f[4]));
        float y5 = fmaf(na1, y4, fmaf(na2, y3, f[5]));
        float y6 = fmaf(na1, y5, fmaf(na2, y4, f[6]));
        float y7 = fmaf(na1, y6, fmaf(na2, y5, f[7]));

        float2 u = make_float2(y6, fmaf(alpha, y6, -y7) * invbeta);
        float2 w = cmulf(u, sd);

#pragma unroll
        for (int s = 16; s > 0; s >>= 1) {
            w.x += __shfl_down_sync(0xffffffffu, w.x, s);
            w.y += __shfl_down_sync(0xffffffffu, w.y, s);
        }
        if (lane == 0) {
            double t1 = cu1 + (double)w.x;
            double t2 = cu2 + (double)w.y;
            cu1 = c256r * t1 - c256i * t2;
            cu2 = c256i * t1 + c256r * t2;
        }
        pv_w = __shfl_sync(0xffffffffu, vb.w, 31);
        pv_z = __shfl_sync(0xffffffffu, vb.z, 31);
        va = nva; vb = nvb;
    }
    if (lane == 0) {
        double e1 = sc.d_alpha * cu1 - sc.d_beta * cu2;   // y[last]
        g_end[wid] = make_double2(e1, cu1);               // (y[last], y[last-1])
    }
}

// ---------------------------------------------------------------------------
// Pass 2: per-row KS scan over 256 chunk states in DOUBLE (vector-only,
// level matrices Phi^(1024*2^r) precomputed by thread 0).  Writes exclusive
// prefixes (chunk start states).
// ---------------------------------------------------------------------------
__global__ __launch_bounds__(256) void k_pass2(const float* __restrict__ ac)
{
    __shared__ double2 sV[CPR];
    __shared__ double  sLev[8 * 4];
    int row = blockIdx.x, tid = threadIdx.x;

    if (tid == 0) {
        double a0 = (double)ac[0];
        double a1 = (double)ac[1] / a0, a2 = (double)ac[2] / a0;
        double m11 = -a1, m12 = -a2, m21 = 1.0, m22 = 0.0;
        for (int i = 0; i < 10; ++i) {   // Phi^1024
            double n11 = m11*m11 + m12*m21, n12 = m11*m12 + m12*m22;
            double n21 = m21*m11 + m22*m21, n22 = m21*m12 + m22*m22;
            m11 = n11; m12 = n12; m21 = n21; m22 = n22;
        }
        sLev[0] = m11; sLev[1] = m12; sLev[2] = m21; sLev[3] = m22;
        for (int r = 1; r < 8; ++r) {
            double n11 = m11*m11 + m12*m21, n12 = m11*m12 + m12*m22;
            double n21 = m21*m11 + m22*m21, n22 = m21*m12 + m22*m22;
            m11 = n11; m12 = n12; m21 = n21; m22 = n22;
            sLev[r*4+0] = m11; sLev[r*4+1] = m12; sLev[r*4+2] = m21; sLev[r*4+3] = m22;
        }
    }
    double2 e = g_end[row * CPR + tid];
    double v1 = e.x, v2 = e.y;
    __syncthreads();

#pragma unroll
    for (int r = 0; r < 8; ++r) {
        sV[tid] = make_double2(v1, v2);
        __syncthreads();
        int src = tid - (1 << r);
        double2 vp;
        bool has = (src >= 0);
        if (has) vp = sV[src];
        __syncthreads();
        if (has) {
            double m11 = sLev[r*4+0], m12 = sLev[r*4+1];
            double m21 = sLev[r*4+2], m22 = sLev[r*4+3];
            v1 = m11 * vp.x + m12 * vp.y + v1;
            v2 = m21 * vp.x + m22 * vp.y + v2;
        }
    }
    sV[tid] = make_double2(v1, v2);
    __syncthreads();
    double2 ex = (tid == 0) ? make_double2(0.0, 0.0) : sV[tid - 1];
    g_start[row * CPR + tid] = ex;
}

// ---------------------------------------------------------------------------
// Pass 3: corrected recompute. Scaled-basis prefix sum; entry state per lane.
// ---------------------------------------------------------------------------
__global__ __launch_bounds__(128, 8) void k_pass3(
    const float* __restrict__ x,
    const float* __restrict__ ac,
    const float* __restrict__ bc,
    const float* __restrict__ gainp,
    float* __restrict__ out)
{
    __shared__ SC sc;
    if (threadIdx.x == 0) build_sc(ac, bc, &sc);
    __syncthreads();

    int wid = blockIdx.x * WPB + (threadIdx.x >> 5);
    int lane = threadIdx.x & 31;
    int row = wid / CPR, chunk = wid - row * CPR;
    size_t wbase = (size_t)row * TT + (size_t)chunk * WSPAN;
    const float4* xv = reinterpret_cast<const float4*>(x + wbase);
    float4* ov = reinterpret_cast<float4*>(out + wbase);

    float na1 = sc.na1, na2 = sc.na2, b0 = sc.b0, b1 = sc.b1, b2 = sc.b2;
    float alpha = sc.alpha, beta = sc.beta, invbeta = sc.invbeta;
    float gain = gainp[0];

    // sd = c^(-8*(lane+1)); su = c^(8*lane)
    float2 sd = sc.i8, su = make_float2(1.f, 0.f);
    if (lane & 1)  { sd = cmulf(sd, sc.ilvl[0]); su = cmulf(su, sc.lvl[0]); }
    if (lane & 2)  { sd = cmulf(sd, sc.ilvl[1]); su = cmulf(su, sc.lvl[1]); }
    if (lane & 4)  { sd = cmulf(sd, sc.ilvl[2]); su = cmulf(su, sc.lvl[2]); }
    if (lane & 8)  { sd = cmulf(sd, sc.ilvl[3]); su = cmulf(su, sc.lvl[3]); }
    if (lane & 16) { sd = cmulf(sd, sc.ilvl[4]); su = cmulf(su, sc.lvl[4]); }

    float pv_w = 0.f, pv_z = 0.f;
    if (chunk) { pv_w = x[wbase - 1]; pv_z = x[wbase - 2]; }

    // warp entry state -> u-space double carry on lane0
    double2 S0 = g_start[wid];
    double cu1 = S0.y;
    double cu2 = (sc.d_alpha * S0.y - S0.x) * sc.d_invbeta;
    double c256r = sc.c256r, c256i = sc.c256i;

    float4 va = xv[2 * lane], vb = xv[2 * lane + 1];
#pragma unroll
    for (int t = 0; t < TILES; ++t) {
        float4 nva, nvb;
        if (t + 1 < TILES) {
            nva = xv[(t + 1) * 64 + 2 * lane];
            nvb = xv[(t + 1) * 64 + 2 * lane + 1];
        }
        float xm1 = __shfl_up_sync(0xffffffffu, vb.w, 1);
        float xm2 = __shfl_up_sync(0xffffffffu, vb.z, 1);
        if (lane == 0) { xm1 = pv_w; xm2 = pv_z; }

        float f[8];
        FIR8(f, va, vb, xm1, xm2, b0, b1, b2);

        float y0 = f[0];
        float y1 = fmaf(na1, y0, f[1]);
        float y2 = fmaf(na1, y1, fmaf(na2, y0, f[2]));
        float y3 = fmaf(na1, y2, fmaf(na2, y1, f[3]));
        float y4 = fmaf(na1, y3, fmaf(na2, y2, f[4]));
        float y5 = fmaf(na1, y4, fmaf(na2, y3, f[5]));
        float y6 = fmaf(na1, y5, fmaf(na2, y4, f[6]));
        float y7 = fmaf(na1, y6, fmaf(na2, y5, f[7]));

        float2 u = make_float2(y6, fmaf(alpha, y6, -y7) * invbeta);
        float2 w = cmulf(u, sd);

        // inclusive prefix SUM
#pragma unroll
        for (int s = 1; s < 32; s <<= 1) {
            float px = __shfl_up_sync(0xffffffffu, w.x, s);
            float py = __shfl_up_sync(0xffffffffu, w.y, s);
            if (lane >= s) { w.x += px; w.y += py; }
        }
        float Sx = __shfl_sync(0xffffffffu, w.x, 31);
        float Sy = __shfl_sync(0xffffffffu, w.y, 31);
        float ex = __shfl_up_sync(0xffffffffu, w.x, 1);
        float ey = __shfl_up_sync(0xffffffffu, w.y, 1);
        if (lane == 0) { ex = 0.f; ey = 0.f; }

        float cfx = __shfl_sync(0xffffffffu, (float)cu1, 0);
        float cfy = __shfl_sync(0xffffffffu, (float)cu2, 0);

        // entry_u = (C + exclusive) * c^(8*lane)
        float2 e = cmulf(make_float2(cfx + ex, cfy + ey), su);
        float yp1 = fmaf(alpha, e.x, -beta * e.y);   // y[n-1]
        float yp2 = e.x;                             // y[n-2]

        float z0 = fmaf(na1, yp1, fmaf(na2, yp2, f[0]));
        float z1 = fmaf(na1, z0, fmaf(na2, yp1, f[1]));
        float z2 = fmaf(na1, z1, fmaf(na2, z0, f[2]));
        float z3 = fmaf(na1, z2, fmaf(na2, z1, f[3]));
        float z4 = fmaf(na1, z3, fmaf(na2, z2, f[4]));
        float z5 = fmaf(na1, z4, fmaf(na2, z3, f[5]));
        float z6 = fmaf(na1, z5, fmaf(na2, z4, f[6]));
        float z7 = fmaf(na1, z6, fmaf(na2, z5, f[7]));

        float4 oa, ob;
        oa.x = gain * fminf(1.f, fmaxf(-1.f, z0));
        oa.y = gain * fminf(1.f, fmaxf(-1.f, z1));
        oa.z = gain * fminf(1.f, fmaxf(-1.f, z2));
        oa.w = gain * fminf(1.f, fmaxf(-1.f, z3));
        ob.x = gain * fminf(1.f, fmaxf(-1.f, z4));
        ob.y = gain * fminf(1.f, fmaxf(-1.f, z5));
        ob.z = gain * fminf(1.f, fmaxf(-1.f, z6));
        ob.w = gain * fminf(1.f, fmaxf(-1.f, z7));
        ov[t * 64 + 2 * lane]     = oa;
        ov[t * 64 + 2 * lane + 1] = ob;

        if (lane == 0) {
            double t1 = cu1 + (double)Sx;
            double t2 = cu2 + (double)Sy;
            cu1 = c256r * t1 - c256i * t2;
            cu2 = c256i * t1 + c256r * t2;
        }
        pv_w = __shfl_sync(0xffffffffu, vb.w, 31);
        pv_z = __shfl_sync(0xffffffffu, vb.z, 31);
        va = nva; vb = nvb;
    }
}

extern "C" void kernel_launch(void* const* d_in, const int* in_sizes, int n_in,
                              void* d_out, int out_size)
{
    const float* x    = (const float*)d_in[0];
    const float* ac   = (const float*)d_in[1];
    const float* bc   = (const float*)d_in[2];
    const float* gain = (const float*)d_in[3];
    float* out = (float*)d_out;

    k_pass1<<<NBLK, 128>>>(x, ac, bc);
    k_pass2<<<BB, 256>>>(ac);
    k_pass3<<<NBLK, 128>>>(x, ac, bc, gain, out);
}

// round 9
// speedup vs baseline: 2.9000x; 1.0400x over previous
#include <cuda_runtime.h>

// x is [B, T] float32.
#define BB 64
#define TT 262144
#define WSPAN 1024                 // samples per warp
#define TILES 4                    // 4 serial tiles of 256 samples (8/lane)
#define CPR (TT / WSPAN)           // 256 chunks per row
#define NW (BB * CPR)              // 16384 warps
#define WPB 8                      // warps per block (256 threads)
#define NBLK (NW / WPB)            // 2048 blocks

// Chunk end states (zero-IC) / corrected start states, y-space FLOAT:
// (y[last], y[last-1]) resp. (y[-1], y[-2]).  pass2 combines in double.
__device__ float2 g_end[NW];
__device__ float2 g_start[NW];

struct SC {
    float2 lvl[5];     // c^(8*2^r), r=0..4
    float2 ilvl[5];    // c^(-8*2^r)
    float2 i8;         // c^-8
    float2 c256;       // c^256 (tile advance)
    float  alpha, beta, invbeta;
    float  na1, na2, b0, b1, b2;
};

__device__ __forceinline__ void build_sc(const float* ac, const float* bc, SC* sc) {
    double a0 = (double)ac[0];
    double a1 = (double)ac[1] / a0, a2 = (double)ac[2] / a0;
    double al = -0.5 * a1;
    double be = sqrt(a2 - al * al);          // r*sin(theta) > 0
    sc->alpha = (float)al; sc->beta = (float)be; sc->invbeta = (float)(1.0 / be);
    sc->na1 = (float)(-a1); sc->na2 = (float)(-a2);
    sc->b0 = (float)((double)bc[0] / a0);
    sc->b1 = (float)((double)bc[1] / a0);
    sc->b2 = (float)((double)bc[2] / a0);

    double cr = al, ci = be;                 // c
    for (int i = 0; i < 3; ++i) { double nr = cr*cr - ci*ci, ni = 2.0*cr*ci; cr = nr; ci = ni; } // c^8
    for (int r = 0; r < 5; ++r) {
        sc->lvl[r] = make_float2((float)cr, (float)ci);
        double n = cr*cr + ci*ci;            // inverse = conj/|.|^2
        sc->ilvl[r] = make_float2((float)(cr / n), (float)(-ci / n));
        if (r == 0) sc->i8 = sc->ilvl[0];
        double nr = cr*cr - ci*ci, ni = 2.0*cr*ci; cr = nr; ci = ni;
    }
    sc->c256 = make_float2((float)cr, (float)ci);   // c^256
}

__device__ __forceinline__ float2 cmulf(float2 a, float2 b) {
    return make_float2(fmaf(a.x, b.x, -a.y * b.y), fmaf(a.x, b.y, a.y * b.x));
}

// 8-sample FIR terms from x0..x7 (va,vb) and two previous samples.
#define FIR8(f, va, vb, xm1, xm2, b0, b1, b2)                         \
    f[0] = fmaf(b1, xm1,  fmaf(b2, xm2,  b0 * va.x));                 \
    f[1] = fmaf(b1, va.x, fmaf(b2, xm1,  b0 * va.y));                 \
    f[2] = fmaf(b1, va.y, fmaf(b2, va.x, b0 * va.z));                 \
    f[3] = fmaf(b1, va.z, fmaf(b2, va.y, b0 * va.w));                 \
    f[4] = fmaf(b1, va.w, fmaf(b2, va.z, b0 * vb.x));                 \
    f[5] = fmaf(b1, vb.x, fmaf(b2, va.w, b0 * vb.y));                 \
    f[6] = fmaf(b1, vb.y, fmaf(b2, vb.x, b0 * vb.z));                 \
    f[7] = fmaf(b1, vb.z, fmaf(b2, vb.y, b0 * vb.w));

// ---------------------------------------------------------------------------
// Pass 1: per-warp zero-IC end state. All-fp32. Scaled-basis complex-sum
// reduce: w_j = b_j * c^(-8(j+1)); S = sum w_j; carry C' = c256*(C + S).
// ---------------------------------------------------------------------------
__global__ __launch_bounds__(256, 5) void k_pass1(
    const float* __restrict__ x,
    const float* __restrict__ ac,
    const float* __restrict__ bc)
{
    __shared__ SC sc;
    if (threadIdx.x == 0) build_sc(ac, bc, &sc);
    __syncthreads();

    int wid = blockIdx.x * WPB + (threadIdx.x >> 5);
    int lane = threadIdx.x & 31;
    int row = wid / CPR, chunk = wid - row * CPR;
    size_t wbase = (size_t)row * TT + (size_t)chunk * WSPAN;
    const float4* xv = reinterpret_cast<const float4*>(x + wbase);

    float na1 = sc.na1, na2 = sc.na2, b0 = sc.b0, b1 = sc.b1, b2 = sc.b2;
    float alpha = sc.alpha, beta = sc.beta, invbeta = sc.invbeta;
    float2 c256 = sc.c256;

    // sd = c^(-8*(lane+1))
    float2 sd = sc.i8;
    if (lane & 1)  sd = cmulf(sd, sc.ilvl[0]);
    if (lane & 2)  sd = cmulf(sd, sc.ilvl[1]);
    if (lane & 4)  sd = cmulf(sd, sc.ilvl[2]);
    if (lane & 8)  sd = cmulf(sd, sc.ilvl[3]);
    if (lane & 16) sd = cmulf(sd, sc.ilvl[4]);

    float pv_w = 0.f, pv_z = 0.f;
    if (chunk) { pv_w = x[wbase - 1]; pv_z = x[wbase - 2]; }

    float2 C = make_float2(0.f, 0.f);   // u-space carry, fp32

    float4 va = xv[2 * lane], vb = xv[2 * lane + 1];
#pragma unroll
    for (int t = 0; t < TILES; ++t) {
        float4 nva, nvb;
        if (t + 1 < TILES) {
            nva = xv[(t + 1) * 64 + 2 * lane];
            nvb = xv[(t + 1) * 64 + 2 * lane + 1];
        }
        float xm1 = __shfl_up_sync(0xffffffffu, vb.w, 1);
        float xm2 = __shfl_up_sync(0xffffffffu, vb.z, 1);
        if (lane == 0) { xm1 = pv_w; xm2 = pv_z; }

        float f[8];
        FIR8(f, va, vb, xm1, xm2, b0, b1, b2);

        float y0 = f[0];
        float y1 = fmaf(na1, y0, f[1]);
        float y2 = fmaf(na1, y1, fmaf(na2, y0, f[2]));
        float y3 = fmaf(na1, y2, fmaf(na2, y1, f[3]));
        float y4 = fmaf(na1, y3, fmaf(na2, y2, f[4]));
        float y5 = fmaf(na1, y4, fmaf(na2, y3, f[5]));
        float y6 = fmaf(na1, y5, fmaf(na2, y4, f[6]));
        float y7 = fmaf(na1, y6, fmaf(na2, y5, f[7]));

        float2 u = make_float2(y6, fmaf(alpha, y6, -y7) * invbeta);
        float2 w = cmulf(u, sd);

#pragma unroll
        for (int s = 16; s > 0; s >>= 1) {
            w.x += __shfl_down_sync(0xffffffffu, w.x, s);
            w.y += __shfl_down_sync(0xffffffffu, w.y, s);
        }
        // broadcast tile total and update fp32 carry uniformly (all lanes)
        float Sx = __shfl_sync(0xffffffffu, w.x, 0);
        float Sy = __shfl_sync(0xffffffffu, w.y, 0);
        C = cmulf(make_float2(C.x + Sx, C.y + Sy), c256);

        pv_w = __shfl_sync(0xffffffffu, vb.w, 31);
        pv_z = __shfl_sync(0xffffffffu, vb.z, 31);
        va = nva; vb = nvb;
    }
    if (lane == 0) {
        // y[last] = alpha*C1 - beta*C2, y[last-1] = C1
        g_end[wid] = make_float2(fmaf(alpha, C.x, -beta * C.y), C.x);
    }
}

// ---------------------------------------------------------------------------
// Pass 2: per-row KS scan over 256 chunk states in DOUBLE (vector-only),
// level matrices Phi^(1024*2^r) by thread 0.  Writes exclusive prefixes.
// ---------------------------------------------------------------------------
__global__ __launch_bounds__(256) void k_pass2(const float* __restrict__ ac)
{
    __shared__ double2 sV[CPR];
    __shared__ double  sLev[8 * 4];
    int row = blockIdx.x, tid = threadIdx.x;

    if (tid == 0) {
        double a0 = (double)ac[0];
        double a1 = (double)ac[1] / a0, a2 = (double)ac[2] / a0;
        double m11 = -a1, m12 = -a2, m21 = 1.0, m22 = 0.0;
        for (int i = 0; i < 10; ++i) {   // Phi^1024
            double n11 = m11*m11 + m12*m21, n12 = m11*m12 + m12*m22;
            double n21 = m21*m11 + m22*m21, n22 = m21*m12 + m22*m22;
            m11 = n11; m12 = n12; m21 = n21; m22 = n22;
        }
        sLev[0] = m11; sLev[1] = m12; sLev[2] = m21; sLev[3] = m22;
        for (int r = 1; r < 8; ++r) {
            double n11 = m11*m11 + m12*m21, n12 = m11*m12 + m12*m22;
            double n21 = m21*m11 + m22*m21, n22 = m21*m12 + m22*m22;
            m11 = n11; m12 = n12; m21 = n21; m22 = n22;
            sLev[r*4+0] = m11; sLev[r*4+1] = m12; sLev[r*4+2] = m21; sLev[r*4+3] = m22;
        }
    }
    float2 e = g_end[row * CPR + tid];
    double v1 = (double)e.x, v2 = (double)e.y;
    __syncthreads();

#pragma unroll
    for (int r = 0; r < 8; ++r) {
        sV[tid] = make_double2(v1, v2);
        __syncthreads();
        int src = tid - (1 << r);
        double2 vp;
        bool has = (src >= 0);
        if (has) vp = sV[src];
        __syncthreads();
        if (has) {
            double m11 = sLev[r*4+0], m12 = sLev[r*4+1];
            double m21 = sLev[r*4+2], m22 = sLev[r*4+3];
            v1 = m11 * vp.x + m12 * vp.y + v1;
            v2 = m21 * vp.x + m22 * vp.y + v2;
        }
    }
    sV[tid] = make_double2(v1, v2);
    __syncthreads();
    double2 ex = (tid == 0) ? make_double2(0.0, 0.0) : sV[tid - 1];
    g_start[row * CPR + tid] = make_float2((float)ex.x, (float)ex.y);
}

// ---------------------------------------------------------------------------
// Pass 3: corrected recompute, all-fp32. Scaled-basis prefix sum.
// entry_u(lane l) = (C + exclusive_l) * c^(8l); carry C' = c256*(C + S).
// ---------------------------------------------------------------------------
__global__ __launch_bounds__(256, 5) void k_pass3(
    const float* __restrict__ x,
    const float* __restrict__ ac,
    const float* __restrict__ bc,
    const float* __restrict__ gainp,
    float* __restrict__ out)
{
    __shared__ SC sc;
    if (threadIdx.x == 0) build_sc(ac, bc, &sc);
    __syncthreads();

    int wid = blockIdx.x * WPB + (threadIdx.x >> 5);
    int lane = threadIdx.x & 31;
    int row = wid / CPR, chunk = wid - row * CPR;
    size_t wbase = (size_t)row * TT + (size_t)chunk * WSPAN;
    const float4* xv = reinterpret_cast<const float4*>(x + wbase);
    float4* ov = reinterpret_cast<float4*>(out + wbase);

    float na1 = sc.na1, na2 = sc.na2, b0 = sc.b0, b1 = sc.b1, b2 = sc.b2;
    float alpha = sc.alpha, beta = sc.beta, invbeta = sc.invbeta;
    float gain = gainp[0];
    float2 c256 = sc.c256;

    // sd = c^(-8*(lane+1)); su = c^(8*lane)
    float2 sd = sc.i8, su = make_float2(1.f, 0.f);
    if (lane & 1)  { sd = cmulf(sd, sc.ilvl[0]); su = cmulf(su, sc.lvl[0]); }
    if (lane & 2)  { sd = cmulf(sd, sc.ilvl[1]); su = cmulf(su, sc.lvl[1]); }
    if (lane & 4)  { sd = cmulf(sd, sc.ilvl[2]); su = cmulf(su, sc.lvl[2]); }
    if (lane & 8)  { sd = cmulf(sd, sc.ilvl[3]); su = cmulf(su, sc.lvl[3]); }
    if (lane & 16) { sd = cmulf(sd, sc.ilvl[4]); su = cmulf(su, sc.lvl[4]); }

    float pv_w = 0.f, pv_z = 0.f;
    if (chunk) { pv_w = x[wbase - 1]; pv_z = x[wbase - 2]; }

    // warp entry state (y-space fp32) -> u-space fp32 carry
    float2 S0 = g_start[wid];
    float2 C = make_float2(S0.y, fmaf(alpha, S0.y, -S0.x) * invbeta);

    float4 va = xv[2 * lane], vb = xv[2 * lane + 1];
#pragma unroll
    for (int t = 0; t < TILES; ++t) {
        float4 nva, nvb;
        if (t + 1 < TILES) {
            nva = xv[(t + 1) * 64 + 2 * lane];
            nvb = xv[(t + 1) * 64 + 2 * lane + 1];
        }
        float xm1 = __shfl_up_sync(0xffffffffu, vb.w, 1);
        float xm2 = __shfl_up_sync(0xffffffffu, vb.z, 1);
        if (lane == 0) { xm1 = pv_w; xm2 = pv_z; }

        float f[8];
        FIR8(f, va, vb, xm1, xm2, b0, b1, b2);

        float y0 = f[0];
        float y1 = fmaf(na1, y0, f[1]);
        float y2 = fmaf(na1, y1, fmaf(na2, y0, f[2]));
        float y3 = fmaf(na1, y2, fmaf(na2, y1, f[3]));
        float y4 = fmaf(na1, y3, fmaf(na2, y2, f[4]));
        float y5 = fmaf(na1, y4, fmaf(na2, y3, f[5]));
        float y6 = fmaf(na1, y5, fmaf(na2, y4, f[6]));
        float y7 = fmaf(na1, y6, fmaf(na2, y5, f[7]));

        float2 u = make_float2(y6, fmaf(alpha, y6, -y7) * invbeta);
        float2 w = cmulf(u, sd);

        // inclusive prefix SUM
#pragma unroll
        for (int s = 1; s < 32; s <<= 1) {
            float px = __shfl_up_sync(0xffffffffu, w.x, s);
            float py = __shfl_up_sync(0xffffffffu, w.y, s);
            if (lane >= s) { w.x += px; w.y += py; }
        }
        float Sx = __shfl_sync(0xffffffffu, w.x, 31);
        float Sy = __shfl_sync(0xffffffffu, w.y, 31);
        float ex = __shfl_up_sync(0xffffffffu, w.x, 1);
        float ey = __shfl_up_sync(0xffffffffu, w.y, 1);
        if (lane == 0) { ex = 0.f; ey = 0.f; }

        // entry_u = (C + exclusive) * c^(8*lane)   (C uniform across warp)
        float2 e = cmulf(make_float2(C.x + ex, C.y + ey), su);
        float yp1 = fmaf(alpha, e.x, -beta * e.y);   // y[n-1]
        float yp2 = e.x;                             // y[n-2]

        float z0 = fmaf(na1, yp1, fmaf(na2, yp2, f[0]));
        float z1 = fmaf(na1, z0, fmaf(na2, yp1, f[1]));
        float z2 = fmaf(na1, z1, fmaf(na2, z0, f[2]));
        float z3 = fmaf(na1, z2, fmaf(na2, z1, f[3]));
        float z4 = fmaf(na1, z3, fmaf(na2, z2, f[4]));
        float z5 = fmaf(na1, z4, fmaf(na2, z3, f[5]));
        float z6 = fmaf(na1, z5, fmaf(na2, z4, f[6]));
        float z7 = fmaf(na1, z6, fmaf(na2, z5, f[7]));

        float4 oa, ob;
        oa.x = gain * fminf(1.f, fmaxf(-1.f, z0));
        oa.y = gain * fminf(1.f, fmaxf(-1.f, z1));
        oa.z = gain * fminf(1.f, fmaxf(-1.f, z2));
        oa.w = gain * fminf(1.f, fmaxf(-1.f, z3));
        ob.x = gain * fminf(1.f, fmaxf(-1.f, z4));
        ob.y = gain * fminf(1.f, fmaxf(-1.f, z5));
        ob.z = gain * fminf(1.f, fmaxf(-1.f, z6));
        ob.w = gain * fminf(1.f, fmaxf(-1.f, z7));
        ov[t * 64 + 2 * lane]     = oa;
        ov[t * 64 + 2 * lane + 1] = ob;

        // uniform fp32 carry update
        C = cmulf(make_float2(C.x + Sx, C.y + Sy), c256);

        pv_w = __shfl_sync(0xffffffffu, vb.w, 31);
        pv_z = __shfl_sync(0xffffffffu, vb.z, 31);
        va = nva; vb = nvb;
    }
}

extern "C" void kernel_launch(void* const* d_in, const int* in_sizes, int n_in,
                              void* d_out, int out_size)
{
    const float* x    = (const float*)d_in[0];
    const float* ac   = (const float*)d_in[1];
    const float* bc   = (const float*)d_in[2];
    const float* gain = (const float*)d_in[3];
    float* out = (float*)d_out;

    k_pass1<<<NBLK, 256>>>(x, ac, bc);
    k_pass2<<<BB, 256>>>(ac);
    k_pass3<<<NBLK, 256>>>(x, ac, bc, gain, out);
}